// round 5
// baseline (speedup 1.0000x reference)
#include <cuda_runtime.h>
#include <math.h>

// ---------------------------------------------------------------------------
// MAPHead: probe-attention pooling + MLP block.
// Shapes: N=32, L=4096, D=768, H=12, DH=64, MLP=3072. Output [32,768] f32.
//
// q = (probe@wq + bq)/8 is batch-independent (single query), so:
//   logits[n,h,l] = x[n,l,:] . wkq[:,h] + cb[h]   (pass 1)
//   p             = softmax_l(logits)              (pass 2, exact)
//   xbar[n,h,:]   = sum_l p[n,h,l] * x[n,l,:]      (pass 3, f32x2 FMA)
//   o -> xa -> LN -> MLP on [32,768] only          (epilogue)
// ---------------------------------------------------------------------------

#define NB   32
#define LSEQ 4096
#define DM   768
#define NH   12
#define DH   64
#define MLPD 3072

#define NCHUNK 32              // L-chunks for pass 1 (128 rows each)
#define CROWS  (LSEQ/NCHUNK)
#define TR     16              // rows per smem tile in pass 1
#define NTILE  (CROWS/TR)
#define XPAD   772             // padded smem row stride (768+4)

#define LSPLIT 16              // L-splits for pass 3 (256 rows each)

// ------------------------------ scratch -------------------------------------
__device__ float  g_qvec[NH*DH];
__device__ float  g_wkq[NH*DM];                       // [h][d]
__device__ float  g_cb[NH];
__device__ float  g_logits[(size_t)NB*NH*LSEQ];       // [n][h][l]  6.3MB
__device__ float2 g_p2[(size_t)NB*NH*LSEQ];           // (p,p) pairs 12.6MB
__device__ unsigned long long g_part[(size_t)NB*LSPLIT*NH*DM/2];  // 18.9MB
__device__ float  g_xbar[NB*NH*DM];
__device__ float  g_xa[NB*DM];
__device__ float  g_h1[NB*MLPD];

// ------------------------------ prep 1: qvec ---------------------------------
__global__ void prep_qvec(const float* __restrict__ probe,
                          const float* __restrict__ wq,
                          const float* __restrict__ bq) {
    __shared__ float ps[DM];
    int t = threadIdx.x, h = blockIdx.x;
    for (int i = t; i < DM; i += 256) ps[i] = probe[i];
    __syncthreads();
    if (t < DH) {
        int e = t;
        float acc = 0.f;
        const float* w = wq + h*DH + e;
        #pragma unroll 4
        for (int d = 0; d < DM; ++d) acc = fmaf(ps[d], w[(size_t)d*(NH*DH)], acc);
        g_qvec[h*DH + e] = (acc + bq[h*DH + e]) * 0.125f;
    }
}

// ------------------------------ prep 2: wkq, cb ------------------------------
__global__ void prep_wkq(const float* __restrict__ wk,
                         const float* __restrict__ bk) {
    int idx = blockIdx.x*256 + threadIdx.x;
    if (idx < NH*DM) {
        int d = idx / NH, h = idx - d*NH;
        float acc = 0.f;
        const float* w = wk + (size_t)d*(NH*DH) + h*DH;
        const float* q = g_qvec + h*DH;
        #pragma unroll 8
        for (int e = 0; e < DH; ++e) acc = fmaf(w[e], q[e], acc);
        g_wkq[h*DM + d] = acc;
    }
    if (blockIdx.x == 0 && threadIdx.x < NH) {
        int h = threadIdx.x;
        float acc = 0.f;
        const float* q = g_qvec + h*DH;
        for (int e = 0; e < DH; ++e) acc = fmaf(bk[h*DH + e], q[e], acc);
        g_cb[h] = acc;
    }
}

// ------------------------------ pass 1: logits -------------------------------
// grid (NCHUNK, NB), block 256. Thread (r,h) computes one 768-dot from smem.
// Low register footprint (4 accumulators) -> no spill.
#define SM1_X   0
#define SM1_W   (TR*XPAD)
#define SM1_TOT (SM1_W + NH*XPAD)        // 21616 floats = 86464 B

__global__ void __launch_bounds__(256, 2)
k_logits(const float* __restrict__ x) {
    extern __shared__ float sm[];
    const int t = threadIdx.x, chunk = blockIdx.x, n = blockIdx.y;

    // stage wkq [12][768] into smem
    {
        const float4* src = (const float4*)g_wkq;
        for (int i = 0; i < 9; ++i) {
            int fi = i*256 + t;
            if (fi < NH*(DM/4)) {
                int h = fi / (DM/4), c4 = fi - h*(DM/4);
                ((float4*)(sm + SM1_W + h*XPAD))[c4] = src[h*(DM/4) + c4];
            }
        }
    }
    const int ra = t / NH;
    const int ha = t - ra*NH;
    const float cb = (t < TR*NH) ? g_cb[ha] : 0.f;
    const size_t xbase = ((size_t)n*LSEQ + (size_t)chunk*CROWS) * DM;
    float* lrow = g_logits + ((size_t)n*NH + ha)*LSEQ + chunk*CROWS;
    __syncthreads();

    for (int tile = 0; tile < NTILE; ++tile) {
        const float4* gx = (const float4*)(x + xbase + (size_t)tile*TR*DM);
        #pragma unroll
        for (int i = 0; i < 12; ++i) {
            int fi = i*256 + t;
            int r = fi / (DM/4), c4 = fi - r*(DM/4);
            ((float4*)(sm + SM1_X + r*XPAD))[c4] = gx[r*(DM/4) + c4];
        }
        __syncthreads();

        if (t < TR*NH) {
            const float4* xr = (const float4*)(sm + SM1_X + ra*XPAD);
            const float4* wr = (const float4*)(sm + SM1_W + ha*XPAD);
            float s0=0.f, s1=0.f, s2=0.f, s3=0.f;
            #pragma unroll 8
            for (int i = 0; i < DM/4; ++i) {
                float4 a = xr[i], b = wr[i];
                s0 = fmaf(a.x, b.x, s0);
                s1 = fmaf(a.y, b.y, s1);
                s2 = fmaf(a.z, b.z, s2);
                s3 = fmaf(a.w, b.w, s3);
            }
            lrow[tile*TR + ra] = (s0+s1) + (s2+s3) + cb;
        }
        __syncthreads();
    }
}

// ------------------------------ pass 2: softmax ------------------------------
// grid (NH, NB), block 256; exact softmax over L=4096, writes (p,p) pairs.
__global__ void k_softmax() {
    __shared__ float red[256];
    int h = blockIdx.x, n = blockIdx.y, t = threadIdx.x;
    size_t base = ((size_t)n*NH + h)*LSEQ;
    float v[16];
    float M = -1e30f;
    #pragma unroll
    for (int j = 0; j < 16; ++j) {
        v[j] = g_logits[base + j*256 + t];
        M = fmaxf(M, v[j]);
    }
    red[t] = M; __syncthreads();
    for (int s = 128; s > 0; s >>= 1) { if (t < s) red[t] = fmaxf(red[t], red[t+s]); __syncthreads(); }
    M = red[0]; __syncthreads();
    float S = 0.f;
    #pragma unroll
    for (int j = 0; j < 16; ++j) { v[j] = __expf(v[j] - M); S += v[j]; }
    red[t] = S; __syncthreads();
    for (int s = 128; s > 0; s >>= 1) { if (t < s) red[t] += red[t+s]; __syncthreads(); }
    float inv = 1.f / red[0];
    #pragma unroll
    for (int j = 0; j < 16; ++j) {
        float p = v[j] * inv;
        g_p2[base + j*256 + t] = make_float2(p, p);
    }
}

// ------------------------------ pass 3: xbar (f32x2) -------------------------
// grid (LSPLIT, NB), block 384. Thread owns 2 columns; acc[12] packed f32x2.
__global__ void __launch_bounds__(384)
k_xbar(const float* __restrict__ x) {
    __shared__ unsigned long long p2s[NH*256];   // [h][r], (p,p) pairs
    const int t = threadIdx.x, s = blockIdx.x, n = blockIdx.y;
    const int r0 = s * (LSEQ/LSPLIT);

    const unsigned long long* gp = (const unsigned long long*)g_p2;
    for (int i = t; i < NH*256; i += 384) {
        int h = i >> 8, r = i & 255;
        p2s[i] = gp[((size_t)n*NH + h)*LSEQ + r0 + r];
    }

    unsigned long long acc[NH];
    #pragma unroll
    for (int h = 0; h < NH; ++h) acc[h] = 0ULL;   // (0.f, 0.f)

    const unsigned long long* xq =
        (const unsigned long long*)(x + ((size_t)n*LSEQ + r0)*DM);
    __syncthreads();

    for (int r = 0; r < 256; ++r) {
        unsigned long long xv = xq[(size_t)r*(DM/2) + t];
        #pragma unroll
        for (int h = 0; h < NH; ++h)
            asm("fma.rn.f32x2 %0, %1, %2, %0;"
                : "+l"(acc[h]) : "l"(p2s[h*256 + r]), "l"(xv));
    }

    #pragma unroll
    for (int h = 0; h < NH; ++h)
        g_part[(((size_t)(n*LSPLIT + s)*NH) + h)*(DM/2) + t] = acc[h];
}

// ------------------------------ merge partials -------------------------------
// grid (NH, NB), block 256 -> g_xbar[n][h][d]
__global__ void k_merge() {
    int h = blockIdx.x, n = blockIdx.y, t = threadIdx.x;
    const float* pf = (const float*)g_part;
    #pragma unroll
    for (int j = 0; j < 3; ++j) {
        int d = j*256 + t;
        float a = 0.f;
        #pragma unroll 4
        for (int s = 0; s < LSPLIT; ++s)
            a += pf[(((size_t)(n*LSPLIT + s)*NH) + h)*DM + d];
        g_xbar[((size_t)n*NH + h)*DM + d] = a;
    }
}

// ------------------------------ o = xbar@wv+bv ; xa = o@wo+bo ----------------
__global__ void map_proj(const float* __restrict__ wv, const float* __restrict__ bv,
                         const float* __restrict__ wo, const float* __restrict__ bo) {
    __shared__ float xb[NH*DM];
    __shared__ float o_s[NH*DH];
    int n = blockIdx.x, t = threadIdx.x;
    for (int i = 0; i < NH*DM/256; ++i) xb[i*256 + t] = g_xbar[(size_t)n*NH*DM + i*256 + t];
    __syncthreads();
    #pragma unroll
    for (int j = 0; j < 3; ++j) {
        int he = j*256 + t;
        int h = he >> 6;
        float a = bv[he];
        const float* xh = xb + h*DM;
        #pragma unroll 4
        for (int d = 0; d < DM; ++d) a = fmaf(xh[d], wv[(size_t)d*(NH*DH) + he], a);
        o_s[he] = a;
    }
    __syncthreads();
    #pragma unroll
    for (int j = 0; j < 3; ++j) {
        int d = j*256 + t;
        float a = bo[d];
        #pragma unroll 4
        for (int he = 0; he < NH*DH; ++he) a = fmaf(o_s[he], wo[(size_t)he*DM + d], a);
        g_xa[(size_t)n*DM + d] = a;
    }
}

// ------------------------------ MLP stage 1 ----------------------------------
__global__ void map_mlp1(const float* __restrict__ ln_s, const float* __restrict__ ln_b,
                         const float* __restrict__ w1,   const float* __restrict__ b1) {
    __shared__ float xa_s[DM];
    __shared__ float y_s[DM];
    __shared__ float red[256];
    int n = blockIdx.y, bj = blockIdx.x, t = threadIdx.x;
    for (int j = 0; j < 3; ++j) xa_s[j*256 + t] = g_xa[(size_t)n*DM + j*256 + t];
    __syncthreads();
    red[t] = xa_s[t] + xa_s[t+256] + xa_s[t+512];
    __syncthreads();
    for (int s = 128; s > 0; s >>= 1) { if (t < s) red[t] += red[t+s]; __syncthreads(); }
    float mu = red[0] * (1.f/DM);
    __syncthreads();
    {
        float d0 = xa_s[t]-mu, d1 = xa_s[t+256]-mu, d2 = xa_s[t+512]-mu;
        red[t] = d0*d0 + d1*d1 + d2*d2;
    }
    __syncthreads();
    for (int s = 128; s > 0; s >>= 1) { if (t < s) red[t] += red[t+s]; __syncthreads(); }
    float rstd = rsqrtf(red[0] * (1.f/DM) + 1e-6f);
    __syncthreads();
    for (int j = 0; j < 3; ++j) {
        int d = j*256 + t;
        y_s[d] = (xa_s[d] - mu) * rstd * ln_s[d] + ln_b[d];
    }
    __syncthreads();
    int k = bj*256 + t;
    float a = b1[k];
    #pragma unroll 4
    for (int d = 0; d < DM; ++d) a = fmaf(y_s[d], w1[(size_t)d*MLPD + k], a);
    float u = 0.7978845608028654f * (a + 0.044715f * a * a * a);
    g_h1[(size_t)n*MLPD + k] = 0.5f * a * (1.f + tanhf(u));
}

// ------------------------------ MLP stage 2 ----------------------------------
__global__ void map_mlp2(const float* __restrict__ w2, const float* __restrict__ b2,
                         float* __restrict__ out) {
    __shared__ float h1_s[MLPD];
    int n = blockIdx.y, bj = blockIdx.x, t = threadIdx.x;
    for (int i = 0; i < MLPD/256; ++i) h1_s[i*256 + t] = g_h1[(size_t)n*MLPD + i*256 + t];
    __syncthreads();
    int d = bj*256 + t;
    float a = b2[d];
    #pragma unroll 4
    for (int k = 0; k < MLPD; ++k) a = fmaf(h1_s[k], w2[(size_t)k*DM + d], a);
    out[(size_t)n*DM + d] = g_xa[(size_t)n*DM + d] + a;
}

// ------------------------------ launcher -------------------------------------
extern "C" void kernel_launch(void* const* d_in, const int* in_sizes, int n_in,
                              void* d_out, int out_size) {
    const float* x     = (const float*)d_in[0];
    const float* probe = (const float*)d_in[1];
    const float* wq    = (const float*)d_in[2];
    const float* bq    = (const float*)d_in[3];
    const float* wk    = (const float*)d_in[4];
    const float* bk    = (const float*)d_in[5];
    const float* wv    = (const float*)d_in[6];
    const float* bv    = (const float*)d_in[7];
    const float* wo    = (const float*)d_in[8];
    const float* bo    = (const float*)d_in[9];
    const float* ln_s  = (const float*)d_in[10];
    const float* ln_b  = (const float*)d_in[11];
    const float* w1    = (const float*)d_in[12];
    const float* b1    = (const float*)d_in[13];
    const float* w2    = (const float*)d_in[14];
    const float* b2    = (const float*)d_in[15];
    float* out = (float*)d_out;

    const int smem1 = SM1_TOT * (int)sizeof(float);   // 86464 B
    cudaFuncSetAttribute(k_logits, cudaFuncAttributeMaxDynamicSharedMemorySize, smem1);

    prep_qvec<<<NH, 256>>>(probe, wq, bq);
    prep_wkq<<<(NH*DM + 255)/256, 256>>>(wk, bk);
    k_logits<<<dim3(NCHUNK, NB), 256, smem1>>>(x);
    k_softmax<<<dim3(NH, NB), 256>>>();
    k_xbar<<<dim3(LSPLIT, NB), 384>>>(x);
    k_merge<<<dim3(NH, NB), 256>>>();
    map_proj<<<NB, 256>>>(wv, bv, wo, bo);
    map_mlp1<<<dim3(MLPD/256, NB), 256>>>(ln_s, ln_b, w1, b1);
    map_mlp2<<<dim3(DM/256, NB), 256>>>(w2, b2, out);
}

// round 6
// speedup vs baseline: 2.2550x; 2.2550x over previous
#include <cuda_runtime.h>
#include <math.h>

// ---------------------------------------------------------------------------
// MAPHead: probe-attention pooling + MLP block.
// N=32, L=4096, D=768, H=12, DH=64, MLP=3072. Output [32,768] f32.
//
// q = (probe@wq + bq)/8 is batch-independent (single query):
//   logits[n,h,l] = x[n,l,:] . wkq[:,h] + cb[h]     (pass 1: warp-per-row)
//   p             = softmax_l(logits)               (pass 2)
//   xbar[n,h,:]   = sum_l p[n,h,l] * x[n,l,:]       (pass 3: f32x2 FMA)
//   o -> xa -> LN -> MLP on [32,768]                (epilogue GEMVs)
// ---------------------------------------------------------------------------

#define NB   32
#define LSEQ 4096
#define DM   768
#define NH   12
#define DH   64
#define MLPD 3072

#define LSPLIT 16              // L-splits for pass 3 (256 rows each)

// ------------------------------ scratch -------------------------------------
__device__ float  g_qvec[NH*DH];
__device__ float  g_wkq[NH*DM];                       // [h][d]
__device__ float  g_cb[NH];
__device__ float  g_logits[(size_t)NB*NH*LSEQ];       // [n][h][l]
__device__ float2 g_p2[(size_t)NB*NH*LSEQ];           // (p,p) pairs
__device__ unsigned long long g_part[(size_t)NB*LSPLIT*NH*DM/2];
__device__ float  g_xbar[NB*NH*DM];
__device__ float  g_o[NB*NH*DH];
__device__ float  g_xa[NB*DM];
__device__ float  g_h1[NB*MLPD];

// ------------------------------ prep 1: qvec ---------------------------------
// grid 12, block 256. thread = (slice, e): slice of 192 d-values, e = head col.
__global__ void prep_qvec(const float* __restrict__ probe,
                          const float* __restrict__ wq,
                          const float* __restrict__ bq) {
    __shared__ float ps[DM];
    __shared__ float red[4][DH];
    int t = threadIdx.x, h = blockIdx.x;
    int e = t & 63, slice = t >> 6;          // 4 slices x 192 d
    for (int i = t; i < DM; i += 256) ps[i] = probe[i];
    __syncthreads();
    float acc = 0.f;
    const float* w = wq + (size_t)(slice*192)*(NH*DH) + h*DH + e;
    #pragma unroll 8
    for (int d = 0; d < 192; ++d) acc = fmaf(ps[slice*192 + d], w[(size_t)d*(NH*DH)], acc);
    red[slice][e] = acc;
    __syncthreads();
    if (t < DH) {
        float s = red[0][t] + red[1][t] + red[2][t] + red[3][t];
        g_qvec[h*DH + t] = (s + bq[h*DH + t]) * 0.125f;
    }
}

// ------------------------------ prep 2: wkq ----------------------------------
__global__ void prep_wkq(const float* __restrict__ wk) {
    int idx = blockIdx.x*256 + threadIdx.x;
    if (idx < NH*DM) {
        int d = idx / NH, h = idx - d*NH;
        float acc = 0.f;
        const float* w = wk + (size_t)d*(NH*DH) + h*DH;
        const float* q = g_qvec + h*DH;
        #pragma unroll
        for (int e = 0; e < DH; ++e) acc = fmaf(w[e], q[e], acc);
        g_wkq[h*DM + d] = acc;
    }
}

// ------------------------------ prep 3: cb (slot-3 filler) -------------------
__global__ void prep_cb(const float* __restrict__ bk) {
    int h = threadIdx.x;
    if (h < NH) {
        float acc = 0.f;
        const float* q = g_qvec + h*DH;
        #pragma unroll
        for (int e = 0; e < DH; ++e) acc = fmaf(bk[h*DH + e], q[e], acc);
        g_cb[h] = acc;
    }
}

// ------------------------------ pass 1: logits (warp-per-row) ----------------
// grid (16, NB), block 256 (8 warps). Each warp: 32 consecutive rows, processed
// 4 at a time with register blocking. x read coalesced from global; wkq in
// smem [h][768] (bank == lane, conflict-free). Butterfly reduce per row.
__global__ void __launch_bounds__(256)
k_logits(const float* __restrict__ x) {
    __shared__ float wks[NH*DM];     // 36 KB
    __shared__ float cbs[NH];
    const int t = threadIdx.x, lane = t & 31, w = t >> 5;
    const int n = blockIdx.y;
    const int row0 = blockIdx.x*256 + w*32;

    for (int i = t; i < NH*DM/4; i += 256)
        ((float4*)wks)[i] = ((const float4*)g_wkq)[i];
    if (t < NH) cbs[t] = g_cb[t];
    __syncthreads();

    const float* xp = x + ((size_t)n*LSEQ + row0)*DM + lane;

    for (int rb = 0; rb < 32; rb += 4) {
        float acc[4][NH];
        #pragma unroll
        for (int r = 0; r < 4; ++r)
            #pragma unroll
            for (int h = 0; h < NH; ++h) acc[r][h] = 0.f;

        const float* xr = xp + (size_t)rb*DM;
        #pragma unroll 4
        for (int j = 0; j < DM/32; ++j) {
            float xv0 = xr[j*32];
            float xv1 = xr[j*32 +   DM];
            float xv2 = xr[j*32 + 2*DM];
            float xv3 = xr[j*32 + 3*DM];
            #pragma unroll
            for (int h = 0; h < NH; ++h) {
                float wv = wks[h*DM + j*32 + lane];
                acc[0][h] = fmaf(xv0, wv, acc[0][h]);
                acc[1][h] = fmaf(xv1, wv, acc[1][h]);
                acc[2][h] = fmaf(xv2, wv, acc[2][h]);
                acc[3][h] = fmaf(xv3, wv, acc[3][h]);
            }
        }
        // butterfly reduce (all lanes end with full sums)
        #pragma unroll
        for (int off = 16; off; off >>= 1)
            #pragma unroll
            for (int r = 0; r < 4; ++r)
                #pragma unroll
                for (int h = 0; h < NH; ++h)
                    acc[r][h] += __shfl_xor_sync(0xffffffffu, acc[r][h], off);
        if (lane < 4) {
            int l = row0 + rb + lane;        // lane r stores row rb+r
            #pragma unroll
            for (int h = 0; h < NH; ++h) {
                float v;
                // select acc[lane][h] without dynamic register indexing:
                v = (lane == 0) ? acc[0][h] : (lane == 1) ? acc[1][h]
                  : (lane == 2) ? acc[2][h] : acc[3][h];
                g_logits[((size_t)n*NH + h)*LSEQ + l] = v + cbs[h];
            }
        }
    }
}

// ------------------------------ pass 2: softmax ------------------------------
// grid (NH, NB), block 256; exact softmax over L=4096, writes (p,p) pairs.
__global__ void k_softmax() {
    __shared__ float red[256];
    int h = blockIdx.x, n = blockIdx.y, t = threadIdx.x;
    size_t base = ((size_t)n*NH + h)*LSEQ;
    float v[16];
    float M = -1e30f;
    #pragma unroll
    for (int j = 0; j < 16; ++j) {
        v[j] = g_logits[base + j*256 + t];
        M = fmaxf(M, v[j]);
    }
    red[t] = M; __syncthreads();
    for (int s = 128; s > 0; s >>= 1) { if (t < s) red[t] = fmaxf(red[t], red[t+s]); __syncthreads(); }
    M = red[0]; __syncthreads();
    float S = 0.f;
    #pragma unroll
    for (int j = 0; j < 16; ++j) { v[j] = __expf(v[j] - M); S += v[j]; }
    red[t] = S; __syncthreads();
    for (int s = 128; s > 0; s >>= 1) { if (t < s) red[t] += red[t+s]; __syncthreads(); }
    float inv = 1.f / red[0];
    #pragma unroll
    for (int j = 0; j < 16; ++j) {
        float p = v[j] * inv;
        g_p2[base + j*256 + t] = make_float2(p, p);
    }
}

// ------------------------------ pass 3: xbar (f32x2) -------------------------
// grid (LSPLIT, NB), block 384. Thread owns 2 columns; acc[12] packed f32x2.
__global__ void __launch_bounds__(384)
k_xbar(const float* __restrict__ x) {
    __shared__ unsigned long long p2s[NH*256];   // [h][r], (p,p) pairs
    const int t = threadIdx.x, s = blockIdx.x, n = blockIdx.y;
    const int r0 = s * (LSEQ/LSPLIT);

    const unsigned long long* gp = (const unsigned long long*)g_p2;
    for (int i = t; i < NH*256; i += 384) {
        int h = i >> 8, r = i & 255;
        p2s[i] = gp[((size_t)n*NH + h)*LSEQ + r0 + r];
    }

    unsigned long long acc[NH];
    #pragma unroll
    for (int h = 0; h < NH; ++h) acc[h] = 0ULL;

    const unsigned long long* xq =
        (const unsigned long long*)(x + ((size_t)n*LSEQ + r0)*DM);
    __syncthreads();

    for (int r = 0; r < 256; ++r) {
        unsigned long long xv = xq[(size_t)r*(DM/2) + t];
        #pragma unroll
        for (int h = 0; h < NH; ++h)
            asm("fma.rn.f32x2 %0, %1, %2, %0;"
                : "+l"(acc[h]) : "l"(p2s[h*256 + r]), "l"(xv));
    }

    #pragma unroll
    for (int h = 0; h < NH; ++h)
        g_part[(((size_t)(n*LSPLIT + s)*NH) + h)*(DM/2) + t] = acc[h];
}

// ------------------------------ merge partials -------------------------------
__global__ void k_merge() {
    int h = blockIdx.x, n = blockIdx.y, t = threadIdx.x;
    const float* pf = (const float*)g_part;
    #pragma unroll
    for (int j = 0; j < 3; ++j) {
        int d = j*256 + t;
        float a = 0.f;
        #pragma unroll
        for (int s = 0; s < LSPLIT; ++s)
            a += pf[(((size_t)(n*LSPLIT + s)*NH) + h)*DM + d];
        g_xbar[((size_t)n*NH + h)*DM + d] = a;
    }
}

// ------------------------------ proj 1: o = xbar@wv + bv ---------------------
// grid (3, NB), block 256. he = bx*256+t.
__global__ void k_proj1(const float* __restrict__ wv, const float* __restrict__ bv) {
    int n = blockIdx.y, he = blockIdx.x*256 + threadIdx.x;
    int h = he >> 6;
    const float* xh = g_xbar + ((size_t)n*NH + h)*DM;
    float a = bv[he];
    #pragma unroll 8
    for (int d = 0; d < DM; ++d) a = fmaf(xh[d], wv[(size_t)d*(NH*DH) + he], a);
    g_o[(size_t)n*(NH*DH) + he] = a;
}

// ------------------------------ proj 2: xa = o@wo + bo -----------------------
// grid (3, NB), block 256. d = bx*256+t.
__global__ void k_proj2(const float* __restrict__ wo, const float* __restrict__ bo) {
    __shared__ float o_s[NH*DH];
    int n = blockIdx.y, t = threadIdx.x, d = blockIdx.x*256 + t;
    for (int i = t; i < NH*DH; i += 256) o_s[i] = g_o[(size_t)n*(NH*DH) + i];
    __syncthreads();
    float a = bo[d];
    #pragma unroll 8
    for (int he = 0; he < NH*DH; ++he) a = fmaf(o_s[he], wo[(size_t)he*DM + d], a);
    g_xa[(size_t)n*DM + d] = a;
}

// ------------------------------ MLP stage 1: LN + gelu(y@w1+b1) --------------
// grid (12, NB), block 256
__global__ void map_mlp1(const float* __restrict__ ln_s, const float* __restrict__ ln_b,
                         const float* __restrict__ w1,   const float* __restrict__ b1) {
    __shared__ float xa_s[DM];
    __shared__ float y_s[DM];
    __shared__ float red[256];
    int n = blockIdx.y, bj = blockIdx.x, t = threadIdx.x;
    for (int j = 0; j < 3; ++j) xa_s[j*256 + t] = g_xa[(size_t)n*DM + j*256 + t];
    __syncthreads();
    red[t] = xa_s[t] + xa_s[t+256] + xa_s[t+512];
    __syncthreads();
    for (int s = 128; s > 0; s >>= 1) { if (t < s) red[t] += red[t+s]; __syncthreads(); }
    float mu = red[0] * (1.f/DM);
    __syncthreads();
    {
        float d0 = xa_s[t]-mu, d1 = xa_s[t+256]-mu, d2 = xa_s[t+512]-mu;
        red[t] = d0*d0 + d1*d1 + d2*d2;
    }
    __syncthreads();
    for (int s = 128; s > 0; s >>= 1) { if (t < s) red[t] += red[t+s]; __syncthreads(); }
    float rstd = rsqrtf(red[0] * (1.f/DM) + 1e-6f);
    __syncthreads();
    for (int j = 0; j < 3; ++j) {
        int d = j*256 + t;
        y_s[d] = (xa_s[d] - mu) * rstd * ln_s[d] + ln_b[d];
    }
    __syncthreads();
    int k = bj*256 + t;
    float a = b1[k];
    #pragma unroll 8
    for (int d = 0; d < DM; ++d) a = fmaf(y_s[d], w1[(size_t)d*MLPD + k], a);
    float u = 0.7978845608028654f * (a + 0.044715f * a * a * a);
    g_h1[(size_t)n*MLPD + k] = 0.5f * a * (1.f + tanhf(u));
}

// ------------------------------ MLP stage 2: out = xa + h1@w2 + b2 -----------
// grid (3, NB), block 256
__global__ void map_mlp2(const float* __restrict__ w2, const float* __restrict__ b2,
                         float* __restrict__ out) {
    __shared__ float h1_s[MLPD];
    int n = blockIdx.y, bj = blockIdx.x, t = threadIdx.x;
    for (int i = 0; i < MLPD/256; ++i) h1_s[i*256 + t] = g_h1[(size_t)n*MLPD + i*256 + t];
    __syncthreads();
    int d = bj*256 + t;
    float a = b2[d];
    #pragma unroll 16
    for (int k = 0; k < MLPD; ++k) a = fmaf(h1_s[k], w2[(size_t)k*DM + d], a);
    out[(size_t)n*DM + d] = g_xa[(size_t)n*DM + d] + a;
}

// ------------------------------ launcher -------------------------------------
extern "C" void kernel_launch(void* const* d_in, const int* in_sizes, int n_in,
                              void* d_out, int out_size) {
    const float* x     = (const float*)d_in[0];
    const float* probe = (const float*)d_in[1];
    const float* wq    = (const float*)d_in[2];
    const float* bq    = (const float*)d_in[3];
    const float* wk    = (const float*)d_in[4];
    const float* bk    = (const float*)d_in[5];
    const float* wv    = (const float*)d_in[6];
    const float* bv    = (const float*)d_in[7];
    const float* wo    = (const float*)d_in[8];
    const float* bo    = (const float*)d_in[9];
    const float* ln_s  = (const float*)d_in[10];
    const float* ln_b  = (const float*)d_in[11];
    const float* w1    = (const float*)d_in[12];
    const float* b1    = (const float*)d_in[13];
    const float* w2    = (const float*)d_in[14];
    const float* b2    = (const float*)d_in[15];
    float* out = (float*)d_out;

    prep_qvec<<<NH, 256>>>(probe, wq, bq);                 // slot 1
    prep_wkq<<<(NH*DM + 255)/256, 256>>>(wk);              // slot 2
    prep_cb<<<1, 32>>>(bk);                                // slot 3 (filler)
    k_logits<<<dim3(16, NB), 256>>>(x);                    // slot 4 <- profiled
    k_softmax<<<dim3(NH, NB), 256>>>();                    // slot 5
    k_xbar<<<dim3(LSPLIT, NB), 384>>>(x);                  // slot 6
    k_merge<<<dim3(NH, NB), 256>>>();                      // slot 7
    k_proj1<<<dim3(3, NB), 256>>>(wv, bv);                 // slot 8
    k_proj2<<<dim3(3, NB), 256>>>(wo, bo);                 // slot 9
    map_mlp1<<<dim3(MLPD/256, NB), 256>>>(ln_s, ln_b, w1, b1);
    map_mlp2<<<dim3(DM/256, NB), 256>>>(w2, b2, out);
}